// round 14
// baseline (speedup 1.0000x reference)
#include <cuda_runtime.h>
#include <cuda_fp16.h>

// Problem constants (BETA = ALPHA = WEIGHT = 1 are compile-time constants in the reference)
#define N_POINTS 4096
#define N_EVENTS 1000000

#define THREADS   256
#define CTAS_SM   6
#define GRID      (148 * CTAS_SM)        // 888 = exactly one wave at 6 CTA/SM
#define NVEC      (N_EVENTS / 4)         // 250000 vec4 event packets

// Circulant pair mapping: pairs (i, (i+d) & 4095), d = 1..2047 for all i (full),
// d = 2048 for i < 2048 (half). Each unordered pair appears exactly once.
// Unit u in [0, 32752): d = (u>>4)+1, chunk = u&15  (256 i's per unit)
// Unit u in [32752, 32760): d = 2048, chunk = u-32752 (i < 2048)
#define UNITS_FULL 32752                 // 2047 * 16
#define UNITS_ALL  32760                 // + 8 half-row units

__device__ float        g_partials[GRID];
__device__ unsigned int g_count;   // zero-init; last block resets it -> graph-replay safe

__device__ __forceinline__ float block_reduce_sum(float v) {
    __shared__ float sdata[THREADS / 32];
    #pragma unroll
    for (int o = 16; o > 0; o >>= 1) v += __shfl_down_sync(0xffffffffu, v, o);
    const int lane = threadIdx.x & 31;
    const int wid  = threadIdx.x >> 5;
    if (lane == 0) sdata[wid] = v;
    __syncthreads();
    if (wid == 0) {
        v = (lane < THREADS / 32) ? sdata[lane] : 0.0f;
        #pragma unroll
        for (int o = (THREADS / 64); o > 0; o >>= 1) v += __shfl_down_sync(0xffffffffu, v, o);
    }
    return v;
}

__global__ __launch_bounds__(THREADS, CTAS_SM)
void smallnet_fused_kernel(const float2* __restrict__ z0,
                           const float2* __restrict__ v0,
                           const float*  __restrict__ event_times,
                           const float*  __restrict__ t0p,
                           const float*  __restrict__ tnp,
                           const int*    __restrict__ u_idx,
                           const int*    __restrict__ v_idx,
                           float* __restrict__ out) {
    // fp16 node table for event gathers: (z.x,z.y) in .x, (v.x,v.y) in .y  (32 KB)
    __shared__ uint2 tbl[N_POINTS];

    const int b   = blockIdx.x;
    const int tid = threadIdx.x;

    // ---------------- build fp16 table (coalesced, all blocks) ----------------
    for (int p = tid; p < N_POINTS; p += THREADS) {
        const float2 z = __ldg(&z0[p]);
        const float2 v = __ldg(&v0[p]);
        __half2 hz = __floats2half2_rn(z.x, z.y);
        __half2 hv = __floats2half2_rn(v.x, v.y);
        uint2 e;
        e.x = *reinterpret_cast<unsigned int*>(&hz);
        e.y = *reinterpret_cast<unsigned int*>(&hv);
        tbl[p] = e;
    }
    __syncthreads();

    float acc_ev = 0.0f;   // event term
    float acc_pi = 0.0f;   // pair integrand sum (pre-scaled)

    // ---------------- event term: sum_e (1 - ||dz0 + dv0*t||^2) ----------------
    {
        const int4*   u4 = (const int4*)u_idx;
        const int4*   v4 = (const int4*)v_idx;
        const float4* t4 = (const float4*)event_times;

        for (int e = b * THREADS + tid; e < NVEC; e += GRID * THREADS) {
            const int4   u = __ldg(&u4[e]);
            const int4   v = __ldg(&v4[e]);
            const float4 t = __ldg(&t4[e]);

            #pragma unroll
            for (int k = 0; k < 4; ++k) {
                const uint2 eu = tbl[(&u.x)[k]];
                const uint2 ev = tbl[(&v.x)[k]];
                const float tt = (&t.x)[k];

                const __half2 hzu = *reinterpret_cast<const __half2*>(&eu.x);
                const __half2 hvu = *reinterpret_cast<const __half2*>(&eu.y);
                const __half2 hzv = *reinterpret_cast<const __half2*>(&ev.x);
                const __half2 hvv = *reinterpret_cast<const __half2*>(&ev.y);

                const float2 dz = __half22float2(__hsub2(hzu, hzv));
                const float2 dv = __half22float2(__hsub2(hvu, hvv));

                const float dx = fmaf(dv.x, tt, dz.x);
                const float dy = fmaf(dv.y, tt, dz.y);
                acc_ev += 1.0f - fmaf(dx, dx, dy * dy);   // beta = 1
            }
        }
    }

    // ---------------- non-event (pair) term: GL-4 quadrature ----------------
    // I = (dt/2) * sum_k w_k * exp(E - u_k^2), E = 1 - cross^2/mn2,
    // all exponents computed in exp2 domain (pre-scaled by log2 e).
    const float t0 = __ldg(t0p);
    const float tn = __ldg(tnp);
    const float dt = tn - t0;

    const float L  = 1.4426950408889634f;   // log2(e)
    const float SL = 1.2011224087864498f;   // sqrt(log2(e))
    const float C0 = 0.06943184420297371f, C1 = 0.33000947820757187f;
    const float C2 = 0.66999052179242810f, C3 = 0.93056815579702620f;
    const float W0 = 0.3478548451374538f,  W1 = 0.6521451548625461f;
    const float dtSL = dt * SL;

    for (int u = b; u < UNITS_ALL; u += GRID) {
        int d, i;
        if (u < UNITS_FULL) {
            d = (u >> 4) + 1;
            i = ((u & 15) << 8) + tid;
        } else {
            d = 2048;
            i = ((u - UNITS_FULL) << 8) + tid;   // i < 2048
        }
        const int j = (i + d) & (N_POINTS - 1);

        const float2 zi = __ldg(&z0[i]);
        const float2 vi = __ldg(&v0[i]);
        const float2 zj = __ldg(&z0[j]);
        const float2 vj = __ldg(&v0[j]);

        const float a  = zi.x - zj.x;
        const float bb = zi.y - zj.y;
        const float m  = vi.x - vj.x;
        const float n  = vi.y - vj.y;

        const float mn2   = fmaf(m, m, n * n);
        const float inv_s = rsqrtf(mn2);             // alpha = 1
        const float cross = fmaf(a, n, -bb * m);
        const float dot   = fmaf(a, m,  bb * n);

        const float s_   = mn2 * inv_s;
        const float isSL = inv_s * SL;
        const float x0s  = fmaf(mn2, t0, dot) * isSL;   // x0 * sqrt(L)
        const float dS   = s_ * dtSL;                   // (x1-x0) * sqrt(L)

        const float cs   = cross * inv_s;
        const float csL  = cs * (-L);
        const float Elog = fmaf(csL, cs, L);            // L*(1 - cross^2/mn2)

        const float u0 = fmaf(C0, dS, x0s);
        const float u1 = fmaf(C1, dS, x0s);
        const float u2 = fmaf(C2, dS, x0s);
        const float u3 = fmaf(C3, dS, x0s);

        const float e0 = exp2f(fmaf(-u0, u0, Elog));
        const float e1 = exp2f(fmaf(-u1, u1, Elog));
        const float e2 = exp2f(fmaf(-u2, u2, Elog));
        const float e3 = exp2f(fmaf(-u3, u3, Elog));

        float g = W0 * e0;
        g = fmaf(W1, e1, g);
        g = fmaf(W1, e2, g);
        g = fmaf(W0, e3, g);
        acc_pi += g;
    }

    // combined partial: event term minus (dt/2)*pair_sum
    const float partial = block_reduce_sum(fmaf(-0.5f * dt, acc_pi, acc_ev));

    // ---- grid-wide deterministic reduction: last block sums all partials ----
    __shared__ bool is_last;
    if (tid == 0) {
        g_partials[b] = partial;
        __threadfence();
        const unsigned int old = atomicAdd(&g_count, 1u);
        is_last = (old == (unsigned int)(GRID - 1));
    }
    __syncthreads();

    if (is_last) {
        __threadfence();
        float s = 0.0f;
        for (int i2 = tid; i2 < GRID; i2 += THREADS) s += g_partials[i2];
        s = block_reduce_sum(s);
        if (tid == 0) {
            out[0]  = s;
            g_count = 0;   // reset for next graph replay
        }
    }
}

extern "C" void kernel_launch(void* const* d_in, const int* in_sizes, int n_in,
                              void* d_out, int out_size) {
    // metadata order: z0[4096,2], v0[4096,2], event_times[1e6], t0[], tn[], u_idx[1e6], v_idx[1e6]
    const float2* z0 = (const float2*)d_in[0];
    const float2* v0 = (const float2*)d_in[1];
    const float*  et = (const float*)d_in[2];
    const float*  t0 = (const float*)d_in[3];
    const float*  tn = (const float*)d_in[4];
    const int*    ui = (const int*)d_in[5];
    const int*    vi = (const int*)d_in[6];
    float* out = (float*)d_out;

    smallnet_fused_kernel<<<GRID, THREADS>>>(z0, v0, et, t0, tn, ui, vi, out);
}

// round 16
// speedup vs baseline: 1.1491x; 1.1491x over previous
#include <cuda_runtime.h>
#include <cuda_fp16.h>

// Problem constants (BETA = ALPHA = WEIGHT = 1 are compile-time constants in the reference)
#define N_POINTS 4096
#define N_EVENTS 1000000

#define THREADS      256
#define EVENT_BLOCKS 128                        // placed FIRST in the grid (overlap with pairs)
#define ROWPAIRS     2048                       // folded rows: rp -> rows {rp, 4094-rp}
#define PAIR_SPLIT   2
#define PAIR_BLOCKS  (ROWPAIRS * PAIR_SPLIT)    // 4096
#define TOTAL_BLOCKS (EVENT_BLOCKS + PAIR_BLOCKS)

__device__ float        g_partials[TOTAL_BLOCKS];
__device__ unsigned int g_count;   // zero-init; last block resets it -> graph-replay safe

// bare EX2 (2 ulp), no library wrapper
__device__ __forceinline__ float ex2(float x) {
    float y;
    asm("ex2.approx.ftz.f32 %0, %1;" : "=f"(y) : "f"(x));
    return y;
}

__device__ __forceinline__ float block_reduce_sum(float v) {
    __shared__ float sdata[THREADS / 32];
    #pragma unroll
    for (int o = 16; o > 0; o >>= 1) v += __shfl_down_sync(0xffffffffu, v, o);
    const int lane = threadIdx.x & 31;
    const int wid  = threadIdx.x >> 5;
    if (lane == 0) sdata[wid] = v;
    __syncthreads();
    if (wid == 0) {
        v = (lane < THREADS / 32) ? sdata[lane] : 0.0f;
        #pragma unroll
        for (int o = (THREADS / 64); o > 0; o >>= 1) v += __shfl_down_sync(0xffffffffu, v, o);
    }
    return v;
}

__global__ __launch_bounds__(THREADS)
void smallnet_fused_kernel(const float2* __restrict__ z0,
                           const float2* __restrict__ v0,
                           const float*  __restrict__ event_times,
                           const float*  __restrict__ t0p,
                           const float*  __restrict__ tnp,
                           const int*    __restrict__ u_idx,
                           const int*    __restrict__ v_idx,
                           float* __restrict__ out) {
    // fp16 node table for event gathers: (z.x,z.y) in .x, (v.x,v.y) in .y  (32 KB)
    __shared__ uint2 tbl[N_POINTS];

    float acc = 0.0f;
    const int b = blockIdx.x;
    float partial;

    if (b >= EVENT_BLOCKS) {
        // ================= non-event (pair) term: GL-4 quadrature =================
        // I = (dt/2) * sum_k w_k * exp(E - u_k^2), E = 1 - cross^2/mn2,
        // all exponents in exp2 domain (pre-scaled by log2 e).
        const float t0 = __ldg(t0p);
        const float tn = __ldg(tnp);
        const float dt = tn - t0;

        const float L  = 1.4426950408889634f;   // log2(e)
        const float SL = 1.2011224087864498f;   // sqrt(log2(e))
        const float C0 = 0.06943184420297371f, C1 = 0.33000947820757187f;
        const float C2 = 0.66999052179242810f, C3 = 0.93056815579702620f;
        const float W0 = 0.3478548451374538f,  W1 = 0.6521451548625461f;
        const float dtSL = dt * SL;

        const int pb   = b - EVENT_BLOCKS;
        const int rp   = pb >> 1;           // folded row pair
        const int half = pb & 1;            // which half of the j-range

        #pragma unroll
        for (int pass = 0; pass < 2; ++pass) {
            const int i = (pass == 0) ? rp : (N_POINTS - 2 - rp);
            if (pass == 1 && i <= rp) break;     // rp == 2047 folds onto itself

            const float2 zi = __ldg(&z0[i]);
            const float2 vi = __ldg(&v0[i]);

            #pragma unroll 4
            for (int j = i + 1 + half * THREADS + threadIdx.x; j < N_POINTS;
                 j += PAIR_SPLIT * THREADS) {
                const float2 zj = __ldg(&z0[j]);
                const float2 vj = __ldg(&v0[j]);

                const float a  = zi.x - zj.x;
                const float bb = zi.y - zj.y;
                const float m  = vi.x - vj.x;
                const float n  = vi.y - vj.y;

                const float mn2   = fmaf(m, m, n * n);
                const float inv_s = rsqrtf(mn2);             // alpha = 1
                const float cross = fmaf(a, n, -bb * m);
                const float dot   = fmaf(a, m,  bb * n);

                const float s_   = mn2 * inv_s;
                const float isSL = inv_s * SL;
                const float x0s  = fmaf(mn2, t0, dot) * isSL;   // x0 * sqrt(L)
                const float dS   = s_ * dtSL;                   // (x1-x0) * sqrt(L)

                const float cs   = cross * inv_s;
                const float csL  = cs * (-L);
                const float Elog = fmaf(csL, cs, L);            // L*(1 - cross^2/mn2)

                const float u0 = fmaf(C0, dS, x0s);
                const float u1 = fmaf(C1, dS, x0s);
                const float u2 = fmaf(C2, dS, x0s);
                const float u3 = fmaf(C3, dS, x0s);

                const float e0 = ex2(fmaf(-u0, u0, Elog));
                const float e1 = ex2(fmaf(-u1, u1, Elog));
                const float e2 = ex2(fmaf(-u2, u2, Elog));
                const float e3 = ex2(fmaf(-u3, u3, Elog));

                float g = W0 * e0;
                g = fmaf(W1, e1, g);
                g = fmaf(W1, e2, g);
                g = fmaf(W0, e3, g);
                acc += g;
            }
        }
        const float tot = block_reduce_sum(acc);
        // integral_sum = (dt/2) * tot; output subtracts it -> negate
        partial = -0.5f * dt * tot;
    } else {
        // ================= event term: sum_e (1 - ||dz0 + dv0*t||^2) =================
        for (int p = threadIdx.x; p < N_POINTS; p += THREADS) {
            const float2 z = __ldg(&z0[p]);
            const float2 v = __ldg(&v0[p]);
            __half2 hz = __floats2half2_rn(z.x, z.y);
            __half2 hv = __floats2half2_rn(v.x, v.y);
            uint2 e;
            e.x = *reinterpret_cast<unsigned int*>(&hz);
            e.y = *reinterpret_cast<unsigned int*>(&hv);
            tbl[p] = e;
        }
        __syncthreads();

        const int4*   u4 = (const int4*)u_idx;
        const int4*   v4 = (const int4*)v_idx;
        const float4* t4 = (const float4*)event_times;
        const int nvec = N_EVENTS / 4;

        for (int e = b * THREADS + threadIdx.x; e < nvec; e += EVENT_BLOCKS * THREADS) {
            const int4   u = __ldg(&u4[e]);
            const int4   v = __ldg(&v4[e]);
            const float4 t = __ldg(&t4[e]);

            #pragma unroll
            for (int k = 0; k < 4; ++k) {
                const uint2 eu = tbl[(&u.x)[k]];
                const uint2 ev = tbl[(&v.x)[k]];
                const float tt = (&t.x)[k];

                const __half2 hzu = *reinterpret_cast<const __half2*>(&eu.x);
                const __half2 hvu = *reinterpret_cast<const __half2*>(&eu.y);
                const __half2 hzv = *reinterpret_cast<const __half2*>(&ev.x);
                const __half2 hvv = *reinterpret_cast<const __half2*>(&ev.y);

                const float2 dz = __half22float2(__hsub2(hzu, hzv));
                const float2 dv = __half22float2(__hsub2(hvu, hvv));

                const float dx = fmaf(dv.x, tt, dz.x);
                const float dy = fmaf(dv.y, tt, dz.y);
                acc += 1.0f - fmaf(dx, dx, dy * dy);   // beta = 1
            }
        }
        partial = block_reduce_sum(acc);
    }

    // ---- grid-wide deterministic reduction: last block sums all partials ----
    __shared__ bool is_last;
    if (threadIdx.x == 0) {
        g_partials[b] = partial;
        __threadfence();
        const unsigned int old = atomicAdd(&g_count, 1u);
        is_last = (old == (unsigned int)(TOTAL_BLOCKS - 1));
    }
    __syncthreads();

    if (is_last) {
        __threadfence();
        float s = 0.0f;
        for (int i = threadIdx.x; i < TOTAL_BLOCKS; i += THREADS) s += g_partials[i];
        s = block_reduce_sum(s);
        if (threadIdx.x == 0) {
            out[0]  = s;
            g_count = 0;   // reset for next graph replay
        }
    }
}

extern "C" void kernel_launch(void* const* d_in, const int* in_sizes, int n_in,
                              void* d_out, int out_size) {
    // metadata order: z0[4096,2], v0[4096,2], event_times[1e6], t0[], tn[], u_idx[1e6], v_idx[1e6]
    const float2* z0 = (const float2*)d_in[0];
    const float2* v0 = (const float2*)d_in[1];
    const float*  et = (const float*)d_in[2];
    const float*  t0 = (const float*)d_in[3];
    const float*  tn = (const float*)d_in[4];
    const int*    ui = (const int*)d_in[5];
    const int*    vi = (const int*)d_in[6];
    float* out = (float*)d_out;

    smallnet_fused_kernel<<<TOTAL_BLOCKS, THREADS>>>(z0, v0, et, t0, tn, ui, vi, out);
}